// round 2
// baseline (speedup 1.0000x reference)
#include <cuda_runtime.h>

// MAM dense: C[m,n] = max_k(A[m,k]*W[n,k]) + min_k(A[m,k]*W[n,k]) + bias[n]
// A: [M,K] row-major, W: [N,K] row-major, bias: [N], C: [M,N] fp32.
//
// alu-pipe (FMNMX) bound kernel: 2 FMNMX + 1 FMUL per product.
// CTA tile 128(M) x 64(N), 256 threads, 8x4 per-thread register tile,
// k-block 16, double-buffered smem with transposed (k-major) tiles.

#define BM 128
#define BN 64
#define BK 16
#define TM 8
#define TN 4
#define AS 132   // smem stride (floats) for A tile rows; 132*4=528B, 16B-aligned, pad kills STS conflicts
#define BS 68    // smem stride for B tile; 68*4=272B, 16B-aligned

__global__ __launch_bounds__(256, 2)
void mam_dense_kernel(const float* __restrict__ A,
                      const float* __restrict__ W,
                      const float* __restrict__ bias,
                      float* __restrict__ C,
                      int M, int N, int K) {
    __shared__ float As[2][BK * AS];
    __shared__ float Bs[2][BK * BS];

    const int t  = threadIdx.x;
    const int tx = t & 15;    // n-direction (16 threads)
    const int ty = t >> 4;    // m-direction (16 threads)

    const int rowBase = blockIdx.y * BM;
    const int colBase = blockIdx.x * BN;

    // ---- gmem load mapping (per k-block): A is 128x16 floats, W is 64x16 ----
    // thread t loads A rows rA and rA+64 (float4 each), W row rA (float4).
    const int rA = t >> 2;           // 0..63
    const int kq = (t & 3) << 2;     // 0,4,8,12

    const float* aPtr0 = A + (size_t)(rowBase + rA) * K + kq;
    const float* aPtr1 = aPtr0 + (size_t)64 * K;
    const float* bPtr  = W + (size_t)(colBase + rA) * K + kq;

    float4 aR0, aR1, bR;

    // ---- preload k-block 0 into smem buffer 0 ----
    aR0 = *(const float4*)(aPtr0);
    aR1 = *(const float4*)(aPtr1);
    bR  = *(const float4*)(bPtr);
    {
        float* as = As[0];
        float* bs = Bs[0];
        as[(kq + 0) * AS + rA]      = aR0.x;
        as[(kq + 1) * AS + rA]      = aR0.y;
        as[(kq + 2) * AS + rA]      = aR0.z;
        as[(kq + 3) * AS + rA]      = aR0.w;
        as[(kq + 0) * AS + rA + 64] = aR1.x;
        as[(kq + 1) * AS + rA + 64] = aR1.y;
        as[(kq + 2) * AS + rA + 64] = aR1.z;
        as[(kq + 3) * AS + rA + 64] = aR1.w;
        bs[(kq + 0) * BS + rA]      = bR.x;
        bs[(kq + 1) * BS + rA]      = bR.y;
        bs[(kq + 2) * BS + rA]      = bR.z;
        bs[(kq + 3) * BS + rA]      = bR.w;
    }
    __syncthreads();

    float mx[TM][TN], mn[TM][TN];
#pragma unroll
    for (int i = 0; i < TM; ++i)
#pragma unroll
        for (int j = 0; j < TN; ++j) {
            mx[i][j] = -3.402823466e38f;
            mn[i][j] =  3.402823466e38f;
        }

    const int NKB = K / BK;   // 64

    for (int kb = 0; kb < NKB; ++kb) {
        const int buf = kb & 1;

        // prefetch next k-block into registers (overlaps with compute below)
        if (kb + 1 < NKB) {
            const int off = (kb + 1) * BK;
            aR0 = *(const float4*)(aPtr0 + off);
            aR1 = *(const float4*)(aPtr1 + off);
            bR  = *(const float4*)(bPtr  + off);
        }

        // ---- compute 16 k-steps from current buffer ----
        const float* as = As[buf];
        const float* bs = Bs[buf];
#pragma unroll
        for (int kk = 0; kk < BK; ++kk) {
            float a[TM], b[TN];
            float4 t0 = *(const float4*)(as + kk * AS + ty * TM);
            float4 t1 = *(const float4*)(as + kk * AS + ty * TM + 4);
            float4 tb = *(const float4*)(bs + kk * BS + tx * TN);
            a[0] = t0.x; a[1] = t0.y; a[2] = t0.z; a[3] = t0.w;
            a[4] = t1.x; a[5] = t1.y; a[6] = t1.z; a[7] = t1.w;
            b[0] = tb.x; b[1] = tb.y; b[2] = tb.z; b[3] = tb.w;
#pragma unroll
            for (int i = 0; i < TM; ++i) {
#pragma unroll
                for (int j = 0; j < TN; ++j) {
                    float p = a[i] * b[j];
                    mx[i][j] = fmaxf(mx[i][j], p);
                    mn[i][j] = fminf(mn[i][j], p);
                }
            }
        }

        // ---- stage prefetched block into the other buffer ----
        if (kb + 1 < NKB) {
            float* asn = As[buf ^ 1];
            float* bsn = Bs[buf ^ 1];
            asn[(kq + 0) * AS + rA]      = aR0.x;
            asn[(kq + 1) * AS + rA]      = aR0.y;
            asn[(kq + 2) * AS + rA]      = aR0.z;
            asn[(kq + 3) * AS + rA]      = aR0.w;
            asn[(kq + 0) * AS + rA + 64] = aR1.x;
            asn[(kq + 1) * AS + rA + 64] = aR1.y;
            asn[(kq + 2) * AS + rA + 64] = aR1.z;
            asn[(kq + 3) * AS + rA + 64] = aR1.w;
            bsn[(kq + 0) * BS + rA]      = bR.x;
            bsn[(kq + 1) * BS + rA]      = bR.y;
            bsn[(kq + 2) * BS + rA]      = bR.z;
            bsn[(kq + 3) * BS + rA]      = bR.w;
            __syncthreads();
        }
    }

    // ---- epilogue: C = mx + mn + bias ----
    const float4 bv = *(const float4*)(bias + colBase + tx * TN);
#pragma unroll
    for (int i = 0; i < TM; ++i) {
        float4 o;
        o.x = mx[i][0] + mn[i][0] + bv.x;
        o.y = mx[i][1] + mn[i][1] + bv.y;
        o.z = mx[i][2] + mn[i][2] + bv.z;
        o.w = mx[i][3] + mn[i][3] + bv.w;
        *(float4*)(C + (size_t)(rowBase + ty * TM + i) * N + colBase + tx * TN) = o;
    }
}

extern "C" void kernel_launch(void* const* d_in, const int* in_sizes, int n_in,
                              void* d_out, int out_size) {
    const float* x      = (const float*)d_in[0];   // [M, K]
    const float* weight = (const float*)d_in[1];   // [N, K]
    const float* bias   = (const float*)d_in[2];   // [N]
    float* out          = (float*)d_out;           // [M, N]

    const int N = in_sizes[2];
    const int K = in_sizes[1] / N;
    const int M = in_sizes[0] / K;

    dim3 grid(N / BN, M / BM);   // (16, 16) for 1024x2048
    mam_dense_kernel<<<grid, 256>>>(x, weight, bias, out, M, N, K);
}

// round 6
// speedup vs baseline: 1.6936x; 1.6936x over previous
#include <cuda_runtime.h>
#include <cstdint>

// MAM dense: C[m,n] = max_k(A[m,k]*W[n,k]) + min_k(A[m,k]*W[n,k]) + bias[n]
// A:[M,K], W:[N,K], bias:[N], C:[M,N], fp32. M=2048, K=1024, N=1024.
//
// alu-pipe (FMNMX) bound. Fixes vs R1: fine-grain tiles (1024 CTAs -> +-1 tile
// per-SM imbalance instead of 2-vs-1), cp.async gmem->smem (no register
// staging), k-contiguous smem with 144B row pitch (conflict-free), stride-8
// B-column ownership per thread (conflict-free B operand loads).

#define BM 64
#define BN 32
#define BK 32
#define PAD 36    // floats per smem row = 144B = 9 x 16B (odd -> conflict-free)
#define NT 128

__global__ __launch_bounds__(NT, 5)
void mam_dense_kernel(const float* __restrict__ A,
                      const float* __restrict__ W,
                      const float* __restrict__ bias,
                      float* __restrict__ C,
                      int M, int N, int K) {
    __shared__ float As[2][BM * PAD];
    __shared__ float Bs[2][BN * PAD];

    const int t  = threadIdx.x;
    const int tx = t & 7;     // n-direction (8)
    const int ty = t >> 3;    // m-direction (16)

    const int rowBase = blockIdx.y * BM;
    const int colBase = blockIdx.x * BN;

    // cp.async mapping: idx = i*NT + t -> row = idx>>3, qword = idx&7
    const int lrow = t >> 3;        // 0..15
    const int lq   = (t & 7) * 4;   // float offset within row: 0,4,...,28

    const float* aG = A + (size_t)(rowBase + lrow) * K + lq;
    const float* bG = W + (size_t)(colBase + lrow) * K + lq;

    const uint32_t asB0 = (uint32_t)__cvta_generic_to_shared(&As[0][0]);
    const uint32_t asB1 = (uint32_t)__cvta_generic_to_shared(&As[1][0]);
    const uint32_t bsB0 = (uint32_t)__cvta_generic_to_shared(&Bs[0][0]);
    const uint32_t bsB1 = (uint32_t)__cvta_generic_to_shared(&Bs[1][0]);
    const uint32_t sOff = (uint32_t)(lrow * PAD + lq) * 4u;

#define LOAD_BLOCK(KB, BUF)                                                          \
    do {                                                                             \
        const float* a0 = aG + (KB) * BK;                                            \
        const float* b0 = bG + (KB) * BK;                                            \
        uint32_t ad = ((BUF) ? asB1 : asB0) + sOff;                                  \
        uint32_t bd = ((BUF) ? bsB1 : bsB0) + sOff;                                  \
        _Pragma("unroll")                                                            \
        for (int i = 0; i < 4; ++i)                                                  \
            asm volatile("cp.async.cg.shared.global [%0], [%1], 16;\n" ::            \
                         "r"(ad + (uint32_t)(i * 16 * PAD * 4)),                     \
                         "l"(a0 + (size_t)i * 16 * K));                              \
        _Pragma("unroll")                                                            \
        for (int i = 0; i < 2; ++i)                                                  \
            asm volatile("cp.async.cg.shared.global [%0], [%1], 16;\n" ::            \
                         "r"(bd + (uint32_t)(i * 16 * PAD * 4)),                     \
                         "l"(b0 + (size_t)i * 16 * K));                              \
        asm volatile("cp.async.commit_group;\n");                                    \
    } while (0)

    float mx[4][4], mn[4][4];
#pragma unroll
    for (int i = 0; i < 4; ++i)
#pragma unroll
        for (int j = 0; j < 4; ++j) {
            mx[i][j] = -3.402823466e38f;
            mn[i][j] =  3.402823466e38f;
        }

    const int NKB = K / BK;

    LOAD_BLOCK(0, 0);

    for (int kb = 0; kb < NKB; ++kb) {
        const int buf = kb & 1;
        asm volatile("cp.async.wait_group 0;\n" ::: "memory");
        __syncthreads();
        if (kb + 1 < NKB) {
            if (buf) LOAD_BLOCK(kb + 1, 0);
            else     LOAD_BLOCK(kb + 1, 1);
        }

        const float* as = As[buf];
        const float* bs = Bs[buf];
#pragma unroll
        for (int kq = 0; kq < BK / 4; ++kq) {
            float4 av[4], bv[4];
#pragma unroll
            for (int i = 0; i < 4; ++i)
                av[i] = *(const float4*)(as + (ty * 4 + i) * PAD + kq * 4);
#pragma unroll
            for (int j = 0; j < 4; ++j)
                bv[j] = *(const float4*)(bs + (tx + 8 * j) * PAD + kq * 4);
#pragma unroll
            for (int i = 0; i < 4; ++i) {
#pragma unroll
                for (int j = 0; j < 4; ++j) {
                    float p0 = av[i].x * bv[j].x;
                    float p1 = av[i].y * bv[j].y;
                    float p2 = av[i].z * bv[j].z;
                    float p3 = av[i].w * bv[j].w;
                    mx[i][j] = fmaxf(mx[i][j], p0); mn[i][j] = fminf(mn[i][j], p0);
                    mx[i][j] = fmaxf(mx[i][j], p1); mn[i][j] = fminf(mn[i][j], p1);
                    mx[i][j] = fmaxf(mx[i][j], p2); mn[i][j] = fminf(mn[i][j], p2);
                    mx[i][j] = fmaxf(mx[i][j], p3); mn[i][j] = fminf(mn[i][j], p3);
                }
            }
        }
        // next iteration's wait+sync protects the buffer we just read
    }

    // epilogue: C = mx + mn + bias
    float bb[4];
#pragma unroll
    for (int j = 0; j < 4; ++j)
        bb[j] = bias[colBase + tx + 8 * j];

#pragma unroll
    for (int i = 0; i < 4; ++i) {
        const size_t rowOff = (size_t)(rowBase + ty * 4 + i) * N + colBase;
#pragma unroll
        for (int j = 0; j < 4; ++j)
            C[rowOff + tx + 8 * j] = mx[i][j] + mn[i][j] + bb[j];
    }
#undef LOAD_BLOCK
}

extern "C" void kernel_launch(void* const* d_in, const int* in_sizes, int n_in,
                              void* d_out, int out_size) {
    const float* x      = (const float*)d_in[0];   // [M, K]
    const float* weight = (const float*)d_in[1];   // [N, K]
    const float* bias   = (const float*)d_in[2];   // [N]
    float* out          = (float*)d_out;           // [M, N]

    const int N = in_sizes[2];
    const int K = in_sizes[1] / N;
    const int M = in_sizes[0] / K;

    dim3 grid(N / BN, M / BM);   // (32, 32) = 1024 CTAs -> ~6.9 per SM
    mam_dense_kernel<<<grid, NT>>>(x, weight, bias, out, M, N, K);
}

// round 7
// speedup vs baseline: 1.7701x; 1.0452x over previous
#include <cuda_runtime.h>
#include <cstdint>

// MAM dense: C[m,n] = max_k(A[m,k]*W[n,k]) + min_k(A[m,k]*W[n,k]) + bias[n]
// A:[M,K], W:[N,K], bias:[N], C:[M,N], fp32. M=2048, K=1024, N=1024.
//
// Issue-count bound (1 inst/SMSP/cyc). FMNMX count is fixed at 2/product;
// this round halves the multiply stream with mul.rn.f32x2 (packed fp32 pair
// multiply, sm_100+). Pack/unpack movs are register-renaming no-ops because
// operands come from 16B-aligned LDS.128 register quads.

#define BM 64
#define BN 32
#define BK 32
#define PAD 36    // floats per smem row = 144B = 9 x 16B (odd -> conflict-free)
#define NT 128

__device__ __forceinline__ unsigned long long mul2(unsigned long long a,
                                                   unsigned long long b) {
    unsigned long long r;
    asm("mul.rn.f32x2 %0, %1, %2;" : "=l"(r) : "l"(a), "l"(b));
    return r;
}

__device__ __forceinline__ void unpack2(unsigned long long d, float& lo, float& hi) {
    asm("mov.b64 {%0, %1}, %2;" : "=f"(lo), "=f"(hi) : "l"(d));
}

__global__ __launch_bounds__(NT, 5)
void mam_dense_kernel(const float* __restrict__ A,
                      const float* __restrict__ W,
                      const float* __restrict__ bias,
                      float* __restrict__ C,
                      int M, int N, int K) {
    __shared__ float As[2][BM * PAD];
    __shared__ float Bs[2][BN * PAD];

    const int t  = threadIdx.x;
    const int tx = t & 7;     // n-direction (8)
    const int ty = t >> 3;    // m-direction (16)

    const int rowBase = blockIdx.y * BM;
    const int colBase = blockIdx.x * BN;

    // cp.async mapping
    const int lrow = t >> 3;        // 0..15
    const int lq   = (t & 7) * 4;   // float offset within row: 0,4,...,28

    const float* aG = A + (size_t)(rowBase + lrow) * K + lq;
    const float* bG = W + (size_t)(colBase + lrow) * K + lq;

    const uint32_t asB0 = (uint32_t)__cvta_generic_to_shared(&As[0][0]);
    const uint32_t asB1 = (uint32_t)__cvta_generic_to_shared(&As[1][0]);
    const uint32_t bsB0 = (uint32_t)__cvta_generic_to_shared(&Bs[0][0]);
    const uint32_t bsB1 = (uint32_t)__cvta_generic_to_shared(&Bs[1][0]);
    const uint32_t sOff = (uint32_t)(lrow * PAD + lq) * 4u;

#define LOAD_BLOCK(KB, BUF)                                                          \
    do {                                                                             \
        const float* a0 = aG + (KB) * BK;                                            \
        const float* b0 = bG + (KB) * BK;                                            \
        uint32_t ad = ((BUF) ? asB1 : asB0) + sOff;                                  \
        uint32_t bd = ((BUF) ? bsB1 : bsB0) + sOff;                                  \
        _Pragma("unroll")                                                            \
        for (int i = 0; i < 4; ++i)                                                  \
            asm volatile("cp.async.cg.shared.global [%0], [%1], 16;\n" ::            \
                         "r"(ad + (uint32_t)(i * 16 * PAD * 4)),                     \
                         "l"(a0 + (size_t)i * 16 * K));                              \
        _Pragma("unroll")                                                            \
        for (int i = 0; i < 2; ++i)                                                  \
            asm volatile("cp.async.cg.shared.global [%0], [%1], 16;\n" ::            \
                         "r"(bd + (uint32_t)(i * 16 * PAD * 4)),                     \
                         "l"(b0 + (size_t)i * 16 * K));                              \
        asm volatile("cp.async.commit_group;\n");                                    \
    } while (0)

    float mx[4][4], mn[4][4];
#pragma unroll
    for (int i = 0; i < 4; ++i)
#pragma unroll
        for (int j = 0; j < 4; ++j) {
            mx[i][j] = -3.402823466e38f;
            mn[i][j] =  3.402823466e38f;
        }

    const int NKB = K / BK;

    LOAD_BLOCK(0, 0);

    for (int kb = 0; kb < NKB; ++kb) {
        const int buf = kb & 1;
        asm volatile("cp.async.wait_group 0;\n" ::: "memory");
        __syncthreads();
        if (kb + 1 < NKB) {
            if (buf) LOAD_BLOCK(kb + 1, 0);
            else     LOAD_BLOCK(kb + 1, 1);
        }

        const float* as = As[buf];
        const float* bs = Bs[buf];
#pragma unroll
        for (int kq = 0; kq < BK / 4; ++kq) {
            // each ulonglong2 = 4 consecutive k-values as two packed f32 pairs
            ulonglong2 av[4], bv[4];
#pragma unroll
            for (int i = 0; i < 4; ++i)
                av[i] = *(const ulonglong2*)(as + (ty * 4 + i) * PAD + kq * 4);
#pragma unroll
            for (int j = 0; j < 4; ++j)
                bv[j] = *(const ulonglong2*)(bs + (tx + 8 * j) * PAD + kq * 4);
#pragma unroll
            for (int i = 0; i < 4; ++i) {
#pragma unroll
                for (int j = 0; j < 4; ++j) {
                    unsigned long long d0 = mul2(av[i].x, bv[j].x);  // p(k0), p(k1)
                    unsigned long long d1 = mul2(av[i].y, bv[j].y);  // p(k2), p(k3)
                    float p0, p1, p2, p3;
                    unpack2(d0, p0, p1);
                    unpack2(d1, p2, p3);
                    mx[i][j] = fmaxf(mx[i][j], p0); mn[i][j] = fminf(mn[i][j], p0);
                    mx[i][j] = fmaxf(mx[i][j], p1); mn[i][j] = fminf(mn[i][j], p1);
                    mx[i][j] = fmaxf(mx[i][j], p2); mn[i][j] = fminf(mn[i][j], p2);
                    mx[i][j] = fmaxf(mx[i][j], p3); mn[i][j] = fminf(mn[i][j], p3);
                }
            }
        }
        // next iteration's wait+sync protects the buffer we just read
    }

    // epilogue: C = mx + mn + bias
    float bb[4];
#pragma unroll
    for (int j = 0; j < 4; ++j)
        bb[j] = bias[colBase + tx + 8 * j];

#pragma unroll
    for (int i = 0; i < 4; ++i) {
        const size_t rowOff = (size_t)(rowBase + ty * 4 + i) * N + colBase;
#pragma unroll
        for (int j = 0; j < 4; ++j)
            C[rowOff + tx + 8 * j] = mx[i][j] + mn[i][j] + bb[j];
    }
#undef LOAD_BLOCK
}

extern "C" void kernel_launch(void* const* d_in, const int* in_sizes, int n_in,
                              void* d_out, int out_size) {
    const float* x      = (const float*)d_in[0];   // [M, K]
    const float* weight = (const float*)d_in[1];   // [N, K]
    const float* bias   = (const float*)d_in[2];   // [N]
    float* out          = (float*)d_out;           // [M, N]

    const int N = in_sizes[2];
    const int K = in_sizes[1] / N;
    const int M = in_sizes[0] / K;

    dim3 grid(N / BN, M / BM);   // (32, 32) = 1024 CTAs -> ~6.9 per SM
    mam_dense_kernel<<<grid, NT>>>(x, weight, bias, out, M, N, K);
}